// round 2
// baseline (speedup 1.0000x reference)
#include <cuda_runtime.h>

#define BB 8
#define CC 64
#define NN 4096
#define KK 20
#define OO 64
#define SLOPE 0.01f

#define NEG_INF __int_as_float(0xff800000)

// Scratch (static device arrays; no runtime allocation)
__device__ float g_xx[BB * NN];            // |x_j|^2
__device__ float g_y1[BB * NN * OO];       // (b, n, o)  W1 @ x
__device__ float g_c [BB * NN * OO];       // (b, n, o)  (W2 - W1) @ x
__device__ int   g_idx[BB * NN * KK];      // top-K neighbor indices

// ---------------------------------------------------------------------------
// Kernel 1: xx[b][n] = sum_c x[b][c][n]^2
// ---------------------------------------------------------------------------
__global__ void k_xx(const float* __restrict__ x) {
    int t = blockIdx.x * blockDim.x + threadIdx.x;   // t = b*NN + n
    if (t >= BB * NN) return;
    int b = t >> 12;            // / 4096
    int n = t & (NN - 1);
    const float* xp = x + (size_t)b * CC * NN + n;
    float s = 0.f;
#pragma unroll
    for (int c = 0; c < CC; ++c) {
        float v = xp[(size_t)c * NN];
        s = fmaf(v, v, s);
    }
    g_xx[t] = s;
}

// ---------------------------------------------------------------------------
// Kernel 2: projections y1 = W[:, :64] @ x, c = (W[:,64:] - W[:, :64]) @ x
// stored transposed: (b, n, o) contiguous in o for fast gather.
// ---------------------------------------------------------------------------
__global__ void k_proj(const float* __restrict__ x, const float* __restrict__ W) {
    __shared__ float Ws[OO * 2 * CC];   // 64 * 128 floats = 32 KB
    int tid = threadIdx.x;
    for (int i = tid; i < OO * 2 * CC; i += blockDim.x) Ws[i] = W[i];
    __syncthreads();

    int t = blockIdx.x * blockDim.x + tid;   // b*NN + n
    if (t >= BB * NN) return;
    int b = t >> 12;
    int n = t & (NN - 1);
    const float* xp = x + (size_t)b * CC * NN + n;

    float xc[CC];
#pragma unroll
    for (int c = 0; c < CC; ++c) xc[c] = xp[(size_t)c * NN];

    float* y1p = g_y1 + (size_t)t * OO;
    float* cp  = g_c  + (size_t)t * OO;
#pragma unroll 4
    for (int o = 0; o < OO; ++o) {
        const float* wr = Ws + o * 2 * CC;
        float a1 = 0.f, a2 = 0.f;
#pragma unroll
        for (int c = 0; c < CC; ++c) {
            a1 = fmaf(wr[c],      xc[c], a1);
            a2 = fmaf(wr[CC + c], xc[c], a2);
        }
        y1p[o] = a1;
        cp[o]  = a2 - a1;
    }
}

// ---------------------------------------------------------------------------
// Kernel 3: fused pairwise inner products + top-K selection.
// Ranking key s_j = 2 * <x_i, x_j> - |x_j|^2   (equivalent ordering to pdist)
// One thread per query point i (x_i in 64 registers), 128 threads / block.
// x_j streamed through shared in 32-column tiles; broadcast LDS.128 feeds
// 4 FMA chains (4 j's at a time) for ILP.
// Top-20 kept in shared (per-thread column), O(1) register threshold reject.
// ---------------------------------------------------------------------------
#define TJ 32
__global__ void __launch_bounds__(128, 1) k_knn(const float* __restrict__ x) {
    __shared__ float xs[CC][TJ];        // 8 KB, tile of x_j (c-major, j contiguous)
    __shared__ float xxs[TJ];
    __shared__ float vals[KK][128];     // 10 KB
    __shared__ int   idxs[KK][128];     // 10 KB

    int tid = threadIdx.x;
    int bpb = NN / 128;                 // 32 blocks per batch
    int b   = blockIdx.x / bpb;
    int i   = (blockIdx.x % bpb) * 128 + tid;
    const float* xb = x + (size_t)b * CC * NN;

    float xi[CC];
#pragma unroll
    for (int c = 0; c < CC; ++c) xi[c] = xb[(size_t)c * NN + i];

#pragma unroll
    for (int k = 0; k < KK; ++k) vals[k][tid] = NEG_INF;
    float vmin = NEG_INF;
    int   minpos = 0;

    for (int j0 = 0; j0 < NN; j0 += TJ) {
        __syncthreads();
        // load tile: consecutive threads -> consecutive j -> coalesced global,
        // conflict-free shared stores.
        for (int q = tid; q < CC * TJ; q += 128) {
            int c  = q >> 5;        // / TJ
            int jj = q & (TJ - 1);
            xs[c][jj] = xb[(size_t)c * NN + j0 + jj];
        }
        if (tid < TJ) xxs[tid] = g_xx[b * NN + j0 + tid];
        __syncthreads();

#pragma unroll
        for (int jj = 0; jj < TJ; jj += 4) {
            float a0 = 0.f, a1 = 0.f, a2 = 0.f, a3 = 0.f;
#pragma unroll
            for (int c = 0; c < CC; ++c) {
                float4 v = *(const float4*)&xs[c][jj];   // broadcast LDS.128
                a0 = fmaf(xi[c], v.x, a0);
                a1 = fmaf(xi[c], v.y, a1);
                a2 = fmaf(xi[c], v.z, a2);
                a3 = fmaf(xi[c], v.w, a3);
            }
            float s0 = 2.f * a0 - xxs[jj + 0];
            float s1 = 2.f * a1 - xxs[jj + 1];
            float s2 = 2.f * a2 - xxs[jj + 2];
            float s3 = 2.f * a3 - xxs[jj + 3];

#pragma unroll
            for (int u = 0; u < 4; ++u) {
                float s = (u == 0) ? s0 : (u == 1) ? s1 : (u == 2) ? s2 : s3;
                if (s > vmin) {
                    vals[minpos][tid] = s;
                    idxs[minpos][tid] = j0 + jj + u;
                    float vm = vals[0][tid];
                    int   mp = 0;
#pragma unroll
                    for (int k = 1; k < KK; ++k) {
                        float v = vals[k][tid];
                        if (v < vm) { vm = v; mp = k; }
                    }
                    vmin = vm; minpos = mp;
                }
            }
        }
    }

    int* op = g_idx + ((size_t)b * NN + i) * KK;
#pragma unroll
    for (int k = 0; k < KK; ++k) op[k] = idxs[k][tid];
}

// ---------------------------------------------------------------------------
// Kernel 4: gather + max + leaky.
// out[b,o,n] = leaky( c[b,n,o] + max_k y1[b, idx[b,n,k], o] )
// block = 256 threads = 64 o-lanes x 4 points; y1 gathers are contiguous
// 256B rows (coalesced), L2 resident.
// ---------------------------------------------------------------------------
__global__ void k_out(float* __restrict__ out) {
    int o  = threadIdx.x & 63;
    int nn = threadIdx.x >> 6;
    int t  = blockIdx.x * 4 + nn;       // b*NN + n
    int b  = t >> 12;
    int n  = t & (NN - 1);

    const int* ip = g_idx + (size_t)t * KK;
    float cadd = g_c[(size_t)t * OO + o];

    float m = NEG_INF;
#pragma unroll
    for (int k = 0; k < KK; ++k) {
        int j = ip[k];
        float v = g_y1[(((size_t)b * NN) + j) * OO + o];
        m = fmaxf(m, v);
    }
    float h = m + cadd;
    out[((size_t)b * OO + o) * NN + n] = (h >= 0.f) ? h : SLOPE * h;
}

// ---------------------------------------------------------------------------
extern "C" void kernel_launch(void* const* d_in, const int* in_sizes, int n_in,
                              void* d_out, int out_size) {
    const float* x = (const float*)d_in[0];   // (8, 64, 4096) fp32
    const float* W = (const float*)d_in[1];   // (64, 128) fp32
    float* out = (float*)d_out;               // (8, 64, 4096) fp32

    k_xx  <<<(BB * NN + 255) / 256, 256>>>(x);
    k_proj<<<(BB * NN + 127) / 128, 128>>>(x, W);
    k_knn <<<BB * NN / 128, 128>>>(x);
    k_out <<<BB * NN / 4, 256>>>(out);
}

// round 5
// speedup vs baseline: 2.6254x; 2.6254x over previous
#include <cuda_runtime.h>
#include <cuda_bf16.h>
#include <cstdint>

#define BB 8
#define CC 64
#define NN 4096
#define KK 20
#define OO 64
#define SLOPE 0.01f
#define NEG_INF __int_as_float(0xff800000)

// ---------------- scratch ----------------
__device__ float         g_xx [BB * NN];
__device__ __nv_bfloat16 g_xhi[BB * NN * CC];   // [b][n][c], 128B rows
__device__ __nv_bfloat16 g_xlo[BB * NN * CC];
__device__ float         g_y1 [BB * NN * OO];
__device__ float         g_c  [BB * NN * OO];
__device__ int           g_idx[BB * NN * KK];

// ---------------- helpers ----------------
__device__ __forceinline__ uint32_t smem_u32(const void* p) {
    uint32_t a;
    asm("{ .reg .u64 t; cvta.to.shared.u64 t, %1; cvt.u32.u64 %0, t; }"
        : "=r"(a) : "l"(p));
    return a;
}
__device__ __forceinline__ uint32_t sw128(uint32_t off) {
    return off ^ ((off >> 3) & 0x70);
}
__device__ __forceinline__ void ldsm4(uint32_t (&r)[4], uint32_t addr) {
    asm volatile("ldmatrix.sync.aligned.m8n8.x4.shared.b16 {%0,%1,%2,%3}, [%4];"
                 : "=r"(r[0]), "=r"(r[1]), "=r"(r[2]), "=r"(r[3]) : "r"(addr));
}
__device__ __forceinline__ void mma16816(float (&d)[4], const uint32_t (&a)[4],
                                         uint32_t b0, uint32_t b1) {
    asm volatile(
        "mma.sync.aligned.m16n8k16.row.col.f32.bf16.bf16.f32 "
        "{%0,%1,%2,%3}, {%4,%5,%6,%7}, {%8,%9}, {%0,%1,%2,%3};"
        : "+f"(d[0]), "+f"(d[1]), "+f"(d[2]), "+f"(d[3])
        : "r"(a[0]), "r"(a[1]), "r"(a[2]), "r"(a[3]), "r"(b0), "r"(b1));
}

// ---------------------------------------------------------------------------
// Kernel 1: fused xx + bf16 hi/lo split, transposed to [b][n][c]
// ---------------------------------------------------------------------------
__global__ void k_pre(const float* __restrict__ x) {
    int t = blockIdx.x * 256 + threadIdx.x;      // b*NN + n
    int b = t >> 12;
    const float* xp = x + (size_t)b * CC * NN + (t & (NN - 1));
    float s = 0.f;
    uint32_t hw[CC / 2], lw[CC / 2];
#pragma unroll
    for (int c2 = 0; c2 < CC / 2; ++c2) {
        float v0 = xp[(size_t)(2 * c2) * NN];
        float v1 = xp[(size_t)(2 * c2 + 1) * NN];
        s = fmaf(v0, v0, s);
        s = fmaf(v1, v1, s);
        __nv_bfloat16 h0 = __float2bfloat16(v0);
        __nv_bfloat16 h1 = __float2bfloat16(v1);
        __nv_bfloat16 l0 = __float2bfloat16(v0 - __bfloat162float(h0));
        __nv_bfloat16 l1 = __float2bfloat16(v1 - __bfloat162float(h1));
        hw[c2] = (uint32_t)__bfloat16_as_ushort(h0) |
                 ((uint32_t)__bfloat16_as_ushort(h1) << 16);
        lw[c2] = (uint32_t)__bfloat16_as_ushort(l0) |
                 ((uint32_t)__bfloat16_as_ushort(l1) << 16);
    }
    g_xx[t] = s;
    uint4* ph = (uint4*)(g_xhi + (size_t)t * CC);
    uint4* pl = (uint4*)(g_xlo + (size_t)t * CC);
#pragma unroll
    for (int q = 0; q < 8; ++q) {
        ph[q] = make_uint4(hw[4*q], hw[4*q+1], hw[4*q+2], hw[4*q+3]);
        pl[q] = make_uint4(lw[4*q], lw[4*q+1], lw[4*q+2], lw[4*q+3]);
    }
}

// ---------------------------------------------------------------------------
// Kernel 2: projections y1 = W1 @ x, c = (W2 - W1) @ x
// ---------------------------------------------------------------------------
__global__ void k_proj(const float* __restrict__ x, const float* __restrict__ W) {
    __shared__ float Ws[OO * 2 * CC];
    int tid = threadIdx.x;
    for (int i = tid; i < OO * 2 * CC; i += blockDim.x) Ws[i] = W[i];
    __syncthreads();

    int t = blockIdx.x * blockDim.x + tid;
    int b = t >> 12;
    const float* xp = x + (size_t)b * CC * NN + (t & (NN - 1));
    float xc[CC];
#pragma unroll
    for (int c = 0; c < CC; ++c) xc[c] = xp[(size_t)c * NN];

    float* y1p = g_y1 + (size_t)t * OO;
    float* cp  = g_c  + (size_t)t * OO;
#pragma unroll 4
    for (int o = 0; o < OO; ++o) {
        const float* wr = Ws + o * 2 * CC;
        float a1 = 0.f, a2 = 0.f;
#pragma unroll
        for (int c = 0; c < CC; ++c) {
            a1 = fmaf(wr[c],      xc[c], a1);
            a2 = fmaf(wr[CC + c], xc[c], a2);
        }
        y1p[o] = a1;
        cp[o]  = a2 - a1;
    }
}

// ---------------------------------------------------------------------------
// Kernel 3: mma.sync kNN.  Grid 256 = 8 batches x 32 i-blocks, 256 threads.
// 8 warps; warp w owns 16 i-rows.  j-tiles of 64.  3 bf16 products
// (hh, hl, lh) accumulated fp32 per mma.sync.
// ---------------------------------------------------------------------------
#define SM_AHI 0
#define SM_ALO 16384
#define SM_BHI 32768
#define SM_BLO 40960
#define SM_SCR 49152                       // 8 warps x 16 x 66 floats
#define SM_XX  82944
#define SM_CB  83200                       // 8 warps x 16 x 32 int
#define SMEM_TOTAL 99584
#define SCR_STRIDE 66

__device__ __forceinline__ void tk_insert(float (&tv)[KK], int (&ti)[KK],
                                          float& vmin, int& minpos, float s, int j) {
#pragma unroll
    for (int k = 0; k < KK; ++k)
        if (k == minpos) { tv[k] = s; ti[k] = j; }
    float vm = tv[0]; int mp = 0;
#pragma unroll
    for (int k = 1; k < KK; ++k)
        if (tv[k] < vm) { vm = tv[k]; mp = k; }
    vmin = vm; minpos = mp;
}

__global__ void __launch_bounds__(256) k_knn_mma() {
    extern __shared__ char smem[];
    uint32_t sb = smem_u32(smem);
    int tid = threadIdx.x;
    int w   = tid >> 5;
    int l   = tid & 31;
    int b   = blockIdx.x >> 5;
    int ib  = blockIdx.x & 31;

    // ---- stage A tiles (128 rows x 64 bf16, hi+lo), sw128 swizzled ----
    {
        const uint4* Ah = (const uint4*)(g_xhi + ((size_t)b * NN + ib * 128) * CC);
        const uint4* Al = (const uint4*)(g_xlo + ((size_t)b * NN + ib * 128) * CC);
        for (int q = tid; q < 1024; q += 256) {
            uint32_t sw = sw128((uint32_t)q * 16);
            *(uint4*)(smem + SM_AHI + sw) = Ah[q];
            *(uint4*)(smem + SM_ALO + sw) = Al[q];
        }
    }

    float* scr  = (float*)(smem + SM_SCR) + w * (16 * SCR_STRIDE);
    float* xxs  = (float*)(smem + SM_XX);
    int*   cbuf = (int*)(smem + SM_CB) + w * (16 * 32);

    // ldmatrix source addresses (within-warp lane roles)
    // A: row = w*16 + (l&15), chunk16 = ks*2 + (l>>4)
    uint32_t aRow = (uint32_t)(w * 16 + (l & 15));
    uint32_t aChunkBase = (uint32_t)(l >> 4);
    // B: row = p*16 + (l&7) + ((l>>4)&1)*8, chunk16 = ks*2 + ((l>>3)&1)
    uint32_t bRowL  = (uint32_t)((l & 7) + ((l >> 4) & 1) * 8);
    uint32_t bChunk = (uint32_t)((l >> 3) & 1);

    int   srow    = l >> 1;                 // local row this lane scans
    int   colbase = (l & 1) * 32;
    const float* srowp = scr + srow * SCR_STRIDE;

    float tv[KK]; int ti[KK];
    float vmin = NEG_INF; int minpos = 0;

    for (int t = 0; t < 64; ++t) {
        int j0 = t * 64;
        // ---- stage B tile (64 rows x 64 bf16, hi+lo) ----
        {
            const uint4* Bh = (const uint4*)(g_xhi + ((size_t)b * NN + j0) * CC);
            const uint4* Bl = (const uint4*)(g_xlo + ((size_t)b * NN + j0) * CC);
            for (int q = tid; q < 512; q += 256) {
                uint32_t sw = sw128((uint32_t)q * 16);
                *(uint4*)(smem + SM_BHI + sw) = Bh[q];
                *(uint4*)(smem + SM_BLO + sw) = Bl[q];
            }
            if (tid < 64) xxs[tid] = g_xx[b * NN + j0 + tid];
        }
        __syncthreads();

        // ---- compute 16x64 scores per warp ----
        float acc[8][4];
#pragma unroll
        for (int nt = 0; nt < 8; ++nt)
#pragma unroll
            for (int q = 0; q < 4; ++q) acc[nt][q] = 0.f;

#pragma unroll
        for (int ks = 0; ks < 4; ++ks) {
            uint32_t aOff = sw128(aRow * 128 + (ks * 2 + aChunkBase) * 16);
            uint32_t ahi[4], alo[4];
            ldsm4(ahi, sb + SM_AHI + aOff);
            ldsm4(alo, sb + SM_ALO + aOff);
#pragma unroll
            for (int p = 0; p < 4; ++p) {
                uint32_t bOff = sw128((p * 16 + bRowL) * 128 + (ks * 2 + bChunk) * 16);
                uint32_t bh[4], bl[4];
                ldsm4(bh, sb + SM_BHI + bOff);
                ldsm4(bl, sb + SM_BLO + bOff);
                mma16816(acc[2*p],     ahi, bh[0], bh[1]);
                mma16816(acc[2*p + 1], ahi, bh[2], bh[3]);
                mma16816(acc[2*p],     ahi, bl[0], bl[1]);
                mma16816(acc[2*p + 1], ahi, bl[2], bl[3]);
                mma16816(acc[2*p],     alo, bh[0], bh[1]);
                mma16816(acc[2*p + 1], alo, bh[2], bh[3]);
            }
        }

        // ---- scores -> smem: s = 2*dot - xx[j] ----
        {
            int r0 = (l >> 2);
            int c0 = 2 * (l & 3);
#pragma unroll
            for (int nt = 0; nt < 8; ++nt) {
                float2 xv = *(const float2*)&xxs[nt * 8 + c0];
                float2 s01, s23;
                s01.x = fmaf(2.f, acc[nt][0], -xv.x);
                s01.y = fmaf(2.f, acc[nt][1], -xv.y);
                s23.x = fmaf(2.f, acc[nt][2], -xv.x);
                s23.y = fmaf(2.f, acc[nt][3], -xv.y);
                *(float2*)&scr[r0       * SCR_STRIDE + nt * 8 + c0] = s01;
                *(float2*)&scr[(r0 + 8) * SCR_STRIDE + nt * 8 + c0] = s23;
            }
        }
        __syncwarp();

        // ---- selection: each lane scans its half-row ----
        if (t == 0) {
#pragma unroll
            for (int q = 0; q < KK; ++q) {
                tv[q] = srowp[colbase + q];
                ti[q] = j0 + colbase + q;
            }
            float vm = tv[0]; int mp = 0;
#pragma unroll
            for (int k = 1; k < KK; ++k)
                if (tv[k] < vm) { vm = tv[k]; mp = k; }
            vmin = vm; minpos = mp;
#pragma unroll
            for (int q = KK; q < 32; ++q) {
                float s = srowp[colbase + q];
                if (s > vmin) tk_insert(tv, ti, vmin, minpos, s, j0 + colbase + q);
            }
        } else {
            int cnt = 0;
#pragma unroll
            for (int q = 0; q < 32; ++q) {
                float s = srowp[colbase + q];
                if (s > vmin) {
                    if (cnt < 16) { cbuf[cnt * 32 + l] = colbase + q; ++cnt; }
                    else tk_insert(tv, ti, vmin, minpos, s, j0 + colbase + q);
                }
            }
            for (int u = 0; u < cnt; ++u) {
                int col = cbuf[u * 32 + l];
                float s = srowp[col];
                if (s > vmin) tk_insert(tv, ti, vmin, minpos, s, j0 + col);
            }
        }
        __syncthreads();
    }

    // ---- exact merge: 2 half-row top-20s -> row top-20 ----
    {
        float* mv = (float*)smem;                 // [128*2][20] vals
        int*   mi = (int*)(smem + 20480);         // [128*2][20] idx
        int rowg = w * 16 + srow;
        int half = l & 1;
#pragma unroll
        for (int k = 0; k < KK; ++k) {
            mv[(rowg * 2 + half) * KK + k] = tv[k];
            mi[(rowg * 2 + half) * KK + k] = ti[k];
        }
        __syncthreads();
        if (tid < 128) {
            float* v  = mv + tid * 2 * KK;
            int*   id = mi + tid * 2 * KK;
            int gi = b * NN + ib * 128 + tid;
            int* op = g_idx + (size_t)gi * KK;
            for (int s = 0; s < KK; ++s) {
                float best = NEG_INF; int bslot = 0;
#pragma unroll
                for (int q = 0; q < 2 * KK; ++q) {
                    float vv = v[q];
                    if (vv > best) { best = vv; bslot = q; }
                }
                op[s] = id[bslot];
                v[bslot] = NEG_INF;
            }
        }
    }
}

// ---------------------------------------------------------------------------
// Kernel 4: gather + max + leaky
// ---------------------------------------------------------------------------
__global__ void k_out(float* __restrict__ out) {
    int o  = threadIdx.x & 63;
    int nn = threadIdx.x >> 6;
    int t  = blockIdx.x * 4 + nn;
    int b  = t >> 12;
    int n  = t & (NN - 1);

    const int* ip = g_idx + (size_t)t * KK;
    float cadd = g_c[(size_t)t * OO + o];

    float m = NEG_INF;
#pragma unroll
    for (int k = 0; k < KK; ++k) {
        int j = ip[k];
        float v = g_y1[(((size_t)b * NN) + j) * OO + o];
        m = fmaxf(m, v);
    }
    float h = m + cadd;
    out[((size_t)b * OO + o) * NN + n] = (h >= 0.f) ? h : SLOPE * h;
}

// ---------------------------------------------------------------------------
extern "C" void kernel_launch(void* const* d_in, const int* in_sizes, int n_in,
                              void* d_out, int out_size) {
    const float* x = (const float*)d_in[0];
    const float* W = (const float*)d_in[1];
    float* out = (float*)d_out;

    static bool attr_set = false;
    if (!attr_set) {
        cudaFuncSetAttribute(k_knn_mma, cudaFuncAttributeMaxDynamicSharedMemorySize,
                             SMEM_TOTAL);
        attr_set = true;
    }

    k_pre    <<<BB * NN / 256, 256>>>(x);
    k_proj   <<<BB * NN / 128, 128>>>(x, W);
    k_knn_mma<<<256, 256, SMEM_TOTAL>>>();
    k_out    <<<BB * NN / 4, 256>>>(out);
}